// round 8
// baseline (speedup 1.0000x reference)
#include <cuda_runtime.h>
#include <cuda_bf16.h>

#define CC 512      // channels
#define DD 512      // context dim
#define BB 8        // batch
#define HWN 16384   // H*W
#define NBK 111     // persistent k1 blocks per batch (888 total = 148 SM x 6 CTA)
#define NSUB 1024   // 16-pos sub-tiles per batch
#define NCH 37      // k2b chunks per batch (3 rows each: 37*3 = 111)
#define STRIDE 17   // smem row stride (conflict-free)
#define SCALE_C 0.04419417382415922f  // 512^-0.5

// Scratch (device globals; no allocations allowed)
__device__ float g_q[BB * CC];               // SCALE * (ctx @ Wq^T + bq)
__device__ float g_qk[BB * CC];              // SCALE * (q @ Wk)
__device__ float g_pooled[BB * NBK * CC];    // per-block unnormalized pooled sums (1.8MB)
__device__ float g_z[BB * NBK];              // per-block sum exp(logit)
__device__ float g_pp[BB * NCH * CC];        // chunk partial pooled
__device__ float g_gate[BB * CC];            // final channel gates

// ---------------------------------------------------------------------------
// k0a: q_scaled[b][o] = SCALE * (ctx[b]·Wq[o,:] + bq[o]).  Grid (64, BB), 256t.
// ---------------------------------------------------------------------------
__global__ void __launch_bounds__(256) k0a_q(const float* __restrict__ ctx,
                                             const float* __restrict__ Wq,
                                             const float* __restrict__ bq) {
    __shared__ float ctxs[DD];
    int b = blockIdx.y, tid = threadIdx.x;
    int lane = tid & 31, warp = tid >> 5;      // 8 warps
    ctxs[tid] = ctx[b * DD + tid];
    ctxs[tid + 256] = ctx[b * DD + tid + 256];
    __syncthreads();
    int o = blockIdx.x * 8 + warp;
    float a = 0.f;
    #pragma unroll
    for (int j = lane; j < DD; j += 32) a += Wq[o * DD + j] * ctxs[j];
    #pragma unroll
    for (int off = 16; off; off >>= 1) a += __shfl_xor_sync(0xffffffffu, a, off);
    if (lane == 0) g_q[b * CC + o] = (a + bq[o]) * SCALE_C;
}

// ---------------------------------------------------------------------------
// k0b: qk[b][c] = sum_o q_s[b][o] * Wk[o][c].  Grid (8 cchunks, BB), 256t.
// ---------------------------------------------------------------------------
__global__ void __launch_bounds__(256) k0b_qk(const float* __restrict__ Wk) {
    __shared__ float qs[CC];
    __shared__ float red[4][64];
    int b = blockIdx.y, tid = threadIdx.x;
    qs[tid] = g_q[b * CC + tid];
    qs[tid + 256] = g_q[b * CC + tid + 256];
    __syncthreads();
    int cl = tid & 63, og = tid >> 6;          // 4 o-groups of 128
    int c = blockIdx.x * 64 + cl;
    float a = 0.f;
    int o0 = og * 128;
    #pragma unroll 8
    for (int o = 0; o < 128; o++) a = fmaf(qs[o0 + o], Wk[(o0 + o) * CC + c], a);
    red[og][cl] = a;
    __syncthreads();
    if (og == 0) g_qk[b * CC + c] = red[0][cl] + red[1][cl] + red[2][cl] + red[3][cl];
}

// ---------------------------------------------------------------------------
// k1: persistent fused logits + exp-weights (no max; |logit| small) + pooling.
// Grid (NBK, BB) = 888 blocks = one balanced wave at 6 CTAs/SM.  Streaming
// (.cs) loads as in the proven R6 kernel.  Block j of batch b handles
// sub-tiles [(j*NSUB)/NBK, ((j+1)*NSUB)/NBK) (9-10), pooled acc in registers.
// ---------------------------------------------------------------------------
__global__ void __launch_bounds__(256, 6) k1_fused(const float* __restrict__ x) {
    __shared__ float xs[CC * STRIDE];      // 34816 B (reused per sub-tile)
    __shared__ float part[16][9];          // per-warp logit partials
    __shared__ float lw[16];               // exp(logit) for current sub-tile

    int j = blockIdx.x, b = blockIdx.y;
    int tid = threadIdx.x;
    int v = tid & 3, g = tid >> 2, warp = tid >> 5, lane = tid & 31;

    const float* qkb = g_qk + b * CC;
    float qc[8];
    #pragma unroll
    for (int k = 0; k < 8; k++) qc[k] = __ldg(qkb + g + 64 * k);

    int s0 = (j * NSUB) / NBK;
    int s1 = ((j + 1) * NSUB) / NBK;
    long bbase = (long)b * (CC * HWN) + v * 4;
    float pl0 = 0.f, pl1 = 0.f;            // pooled acc for c=tid, c=tid+256
    float zsum = 0.f;                      // valid in warp 0

    for (int s = s0; s < s1; s++) {
        // Phase 1: load 512ch x 16pos to smem, fuse logit partial dots
        const float* xp = x + bbase + s * 16;
        float p0 = 0.f, p1 = 0.f, p2 = 0.f, p3 = 0.f;
        #pragma unroll
        for (int k = 0; k < 8; k++) {
            int c = g + 64 * k;
            float4 d = __ldcs((const float4*)(xp + (long)c * HWN));
            float* dst = xs + c * STRIDE + v * 4;
            dst[0] = d.x; dst[1] = d.y; dst[2] = d.z; dst[3] = d.w;
            p0 = fmaf(d.x, qc[k], p0); p1 = fmaf(d.y, qc[k], p1);
            p2 = fmaf(d.z, qc[k], p2); p3 = fmaf(d.w, qc[k], p3);
        }
        // reduce over the 8 channel-groups in this warp sharing v
        #pragma unroll
        for (int off = 4; off <= 16; off <<= 1) {
            p0 += __shfl_xor_sync(0xffffffffu, p0, off);
            p1 += __shfl_xor_sync(0xffffffffu, p1, off);
            p2 += __shfl_xor_sync(0xffffffffu, p2, off);
            p3 += __shfl_xor_sync(0xffffffffu, p3, off);
        }
        if (lane < 4) {                    // lane == v for lanes 0..3
            part[lane * 4 + 0][warp] = p0;
            part[lane * 4 + 1][warp] = p1;
            part[lane * 4 + 2][warp] = p2;
            part[lane * 4 + 3][warp] = p3;
        }
        __syncthreads();

        // Phase 2 (warp 0): finish logits, weights = exp(l), z partial
        if (warp == 0) {
            int t = lane & 15;
            float l = 0.f;
            #pragma unroll
            for (int i = 0; i < 8; i++) l += part[t][i];
            float w = __expf(l);
            if (lane < 16) lw[t] = w;
            float wz = (lane < 16) ? w : 0.f;
            #pragma unroll
            for (int off = 16; off; off >>= 1)
                wz += __shfl_xor_sync(0xffffffffu, wz, off);
            zsum += wz;
        }
        __syncthreads();

        // Phase 3: accumulate pooled partial from smem (2 channels/thread)
        {
            const float* r0 = xs + tid * STRIDE;
            const float* r1 = xs + (tid + 256) * STRIDE;
            #pragma unroll
            for (int t = 0; t < 16; t++) {
                float w = lw[t];
                pl0 = fmaf(w, r0[t], pl0);
                pl1 = fmaf(w, r1[t], pl1);
            }
        }
        __syncthreads();                   // xs reused next iteration
    }

    float* dst = g_pooled + ((long)(b * NBK) + j) * CC;
    dst[tid] = pl0;
    dst[tid + 256] = pl1;
    if (tid == 0) g_z[b * NBK + j] = zsum;
}

// ---------------------------------------------------------------------------
// k2b: chunk partial pooled sums, float4 rows (L2-hot).  Grid (NCH, BB), 128t.
// Each block sums exactly 3 rows of 128 float4.
// ---------------------------------------------------------------------------
__global__ void __launch_bounds__(128) k2b_combine() {
    int ci = blockIdx.x, b = blockIdx.y;
    int t4 = threadIdx.x;                  // float4 column (128 = 512 ch)
    const float4* base = (const float4*)(g_pooled + (long)b * NBK * CC) + ci * 3 * 128 + t4;
    float4 a0 = base[0];
    float4 a1 = base[128];
    float4 a2 = base[256];
    a0.x += a1.x + a2.x; a0.y += a1.y + a2.y;
    a0.z += a1.z + a2.z; a0.w += a1.w + a2.w;
    ((float4*)g_pp)[(b * NCH + ci) * 128 + t4] = a0;
}

// ---------------------------------------------------------------------------
// k2c: Zinv from g_z; pooled = sum chunks * Zinv; gate = Wv@pooled + bv.
// Grid (64, BB), 256t.
// ---------------------------------------------------------------------------
__global__ void __launch_bounds__(256) k2c_gate(const float* __restrict__ Wv,
                                                const float* __restrict__ bv) {
    __shared__ float pooled[CC];
    __shared__ float red[8];
    __shared__ float s_zinv;
    int b = blockIdx.y, tid = threadIdx.x;
    int lane = tid & 31, warp = tid >> 5;

    float z = (tid < NBK) ? g_z[b * NBK + tid] : 0.f;
    #pragma unroll
    for (int off = 16; off; off >>= 1) z += __shfl_xor_sync(0xffffffffu, z, off);
    if (lane == 0) red[warp] = z;
    __syncthreads();
    if (tid == 0) {
        float s = 0.f;
        #pragma unroll
        for (int i = 0; i < 8; i++) s += red[i];
        s_zinv = 1.f / s;
    }
    __syncthreads();
    float zinv = s_zinv;
    #pragma unroll
    for (int h = 0; h < 2; h++) {
        int c = tid + h * 256;
        float a = 0.f;
        #pragma unroll
        for (int ci = 0; ci < NCH; ci++) a += g_pp[(b * NCH + ci) * CC + c];
        pooled[c] = a * zinv;
    }
    __syncthreads();
    int o = blockIdx.x * 8 + warp;
    float a = 0.f;
    #pragma unroll
    for (int jj = lane; jj < CC; jj += 32) a = fmaf(Wv[o * CC + jj], pooled[jj], a);
    #pragma unroll
    for (int off = 16; off; off >>= 1) a += __shfl_xor_sync(0xffffffffu, a, off);
    if (lane == 0) g_gate[b * CC + o] = a + bv[o];
}

// ---------------------------------------------------------------------------
// k3: out = x * gate[b,c]  (R6-proven: 2x float4 per thread, streaming hints)
// ---------------------------------------------------------------------------
__global__ void __launch_bounds__(256) k3_scale(const float4* __restrict__ x,
                                                float4* __restrict__ out) {
    int i0 = blockIdx.x * 512 + threadIdx.x;
    int i1 = i0 + 256;
    float4 a = __ldcs(x + i0);
    float4 d = __ldcs(x + i1);
    float ga = g_gate[i0 >> 12];           // 4096 float4 per (b,c)
    float gd = g_gate[i1 >> 12];
    a.x *= ga; a.y *= ga; a.z *= ga; a.w *= ga;
    d.x *= gd; d.y *= gd; d.z *= gd; d.w *= gd;
    __stcs(out + i0, a);
    __stcs(out + i1, d);
}

// ---------------------------------------------------------------------------
extern "C" void kernel_launch(void* const* d_in, const int* in_sizes, int n_in,
                              void* d_out, int out_size) {
    const float* x   = (const float*)d_in[0];
    const float* ctx = (const float*)d_in[1];
    const float* Wq  = (const float*)d_in[2];
    const float* bq  = (const float*)d_in[3];
    const float* Wk  = (const float*)d_in[4];
    // d_in[5] = bk: constant logit shift per batch -> cancels in softmax
    const float* Wv  = (const float*)d_in[6];
    const float* bv  = (const float*)d_in[7];

    k0a_q<<<dim3(64, BB), 256>>>(ctx, Wq, bq);
    k0b_qk<<<dim3(8, BB), 256>>>(Wk);
    k1_fused<<<dim3(NBK, BB), 256>>>(x);
    k2b_combine<<<dim3(NCH, BB), 128>>>();
    k2c_gate<<<dim3(64, BB), 256>>>(Wv, bv);
    k3_scale<<<(BB * CC * HWN) / (4 * 512), 256>>>((const float4*)x, (float4*)d_out);
}

// round 9
// speedup vs baseline: 1.1609x; 1.1609x over previous
#include <cuda_runtime.h>
#include <cuda_bf16.h>

#define CC 512      // channels
#define DD 512      // context dim
#define BB 8        // batch
#define HWN 16384   // H*W
#define T_SUB 2     // 16-pos sub-tiles per k1 block
#define NB 512      // k1 blocks per batch = HWN / (16*T_SUB)
#define NCH 32      // k2b chunks per batch (16 rows each)
#define STRIDE 17   // smem row stride (conflict-free)
#define SCALE_C 0.04419417382415922f  // 512^-0.5

// Scratch (device globals; no allocations allowed)
__device__ float g_q[BB * CC];               // SCALE * (ctx @ Wq^T + bq)
__device__ float g_qk[BB * CC];              // SCALE * (q @ Wk)
__device__ float g_pooled[BB * NB * CC];     // per-block unnormalized pooled sums (8.4MB)
__device__ float g_z[BB * NB];               // per-block sum exp(logit)
__device__ float g_pp[BB * NCH * CC];        // chunk partial pooled
__device__ float g_gate[BB * CC];            // final channel gates

// ---------------------------------------------------------------------------
// k0a: q_scaled[b][o] = SCALE * (ctx[b]·Wq[o,:] + bq[o]).  Grid (64, BB), 256t.
// ---------------------------------------------------------------------------
__global__ void __launch_bounds__(256) k0a_q(const float* __restrict__ ctx,
                                             const float* __restrict__ Wq,
                                             const float* __restrict__ bq) {
    __shared__ float ctxs[DD];
    int b = blockIdx.y, tid = threadIdx.x;
    int lane = tid & 31, warp = tid >> 5;      // 8 warps
    ctxs[tid] = ctx[b * DD + tid];
    ctxs[tid + 256] = ctx[b * DD + tid + 256];
    __syncthreads();
    int o = blockIdx.x * 8 + warp;
    float a = 0.f;
    #pragma unroll
    for (int j = lane; j < DD; j += 32) a += Wq[o * DD + j] * ctxs[j];
    #pragma unroll
    for (int off = 16; off; off >>= 1) a += __shfl_xor_sync(0xffffffffu, a, off);
    if (lane == 0) g_q[b * CC + o] = (a + bq[o]) * SCALE_C;
}

// ---------------------------------------------------------------------------
// k0b: qk[b][c] = sum_o q_s[b][o] * Wk[o][c].  Grid (8 cchunks, BB), 256t.
// ---------------------------------------------------------------------------
__global__ void __launch_bounds__(256) k0b_qk(const float* __restrict__ Wk) {
    __shared__ float qs[CC];
    __shared__ float red[4][64];
    int b = blockIdx.y, tid = threadIdx.x;
    qs[tid] = g_q[b * CC + tid];
    qs[tid + 256] = g_q[b * CC + tid + 256];
    __syncthreads();
    int cl = tid & 63, og = tid >> 6;          // 4 o-groups of 128
    int c = blockIdx.x * 64 + cl;
    float a = 0.f;
    int o0 = og * 128;
    #pragma unroll 8
    for (int o = 0; o < 128; o++) a = fmaf(qs[o0 + o], Wk[(o0 + o) * CC + c], a);
    red[og][cl] = a;
    __syncthreads();
    if (og == 0) g_qk[b * CC + c] = red[0][cl] + red[1][cl] + red[2][cl] + red[3][cl];
}

// ---------------------------------------------------------------------------
// k1: fused logits + exp-weights (no max; |logit| small) + pooling, looped
// over T_SUB=2 sub-tiles of 16 positions. Grid (NB, BB), 256 threads.
// Identical structure to the proven R6 kernel; only T_SUB changed (4 -> 2)
// to halve block duration and shrink the final-wave tail.
// ---------------------------------------------------------------------------
__global__ void __launch_bounds__(256) k1_fused(const float* __restrict__ x) {
    __shared__ float xs[CC * STRIDE];      // 34816 B (reused per sub-tile)
    __shared__ float part[16][9];          // per-warp logit partials
    __shared__ float lw[16];               // exp(logit) for current sub-tile

    int blk = blockIdx.x, b = blockIdx.y;
    int tid = threadIdx.x;
    int v = tid & 3, g = tid >> 2, warp = tid >> 5, lane = tid & 31;

    const float* qkb = g_qk + b * CC;
    float qc[8];
    #pragma unroll
    for (int k = 0; k < 8; k++) qc[k] = __ldg(qkb + g + 64 * k);

    long base = (long)b * (CC * HWN) + blk * (16 * T_SUB) + v * 4;
    float pl0 = 0.f, pl1 = 0.f;            // pooled acc for c=tid, c=tid+256
    float zsum = 0.f;                      // valid in warp 0

    #pragma unroll
    for (int s = 0; s < T_SUB; s++) {
        // Phase 1: load 512ch x 16pos to smem, fuse logit partial dots
        float p0 = 0.f, p1 = 0.f, p2 = 0.f, p3 = 0.f;
        #pragma unroll
        for (int k = 0; k < 8; k++) {
            int c = g + 64 * k;
            float4 d = __ldcs((const float4*)(x + base + (long)c * HWN + s * 16));
            float* dst = xs + c * STRIDE + v * 4;
            dst[0] = d.x; dst[1] = d.y; dst[2] = d.z; dst[3] = d.w;
            p0 = fmaf(d.x, qc[k], p0); p1 = fmaf(d.y, qc[k], p1);
            p2 = fmaf(d.z, qc[k], p2); p3 = fmaf(d.w, qc[k], p3);
        }
        // reduce over the 8 channel-groups in this warp sharing v
        #pragma unroll
        for (int off = 4; off <= 16; off <<= 1) {
            p0 += __shfl_xor_sync(0xffffffffu, p0, off);
            p1 += __shfl_xor_sync(0xffffffffu, p1, off);
            p2 += __shfl_xor_sync(0xffffffffu, p2, off);
            p3 += __shfl_xor_sync(0xffffffffu, p3, off);
        }
        if (lane < 4) {                    // lane == v for lanes 0..3
            part[lane * 4 + 0][warp] = p0;
            part[lane * 4 + 1][warp] = p1;
            part[lane * 4 + 2][warp] = p2;
            part[lane * 4 + 3][warp] = p3;
        }
        __syncthreads();

        // Phase 2 (warp 0): finish logits, weights = exp(l), z partial
        if (warp == 0) {
            int t = lane & 15;
            float l = 0.f;
            #pragma unroll
            for (int i = 0; i < 8; i++) l += part[t][i];
            float w = __expf(l);
            if (lane < 16) lw[t] = w;
            float wz = (lane < 16) ? w : 0.f;
            #pragma unroll
            for (int off = 16; off; off >>= 1)
                wz += __shfl_xor_sync(0xffffffffu, wz, off);
            zsum += wz;
        }
        __syncthreads();

        // Phase 3: accumulate pooled partial from smem (2 channels/thread)
        {
            const float* r0 = xs + tid * STRIDE;
            const float* r1 = xs + (tid + 256) * STRIDE;
            #pragma unroll
            for (int t = 0; t < 16; t++) {
                float w = lw[t];
                pl0 = fmaf(w, r0[t], pl0);
                pl1 = fmaf(w, r1[t], pl1);
            }
        }
        __syncthreads();                   // xs reused next iteration
    }

    float* dst = g_pooled + ((long)(b * NB) + blk) * CC;
    dst[tid] = pl0;
    dst[tid + 256] = pl1;
    if (tid == 0) g_z[b * NB + blk] = zsum;
}

// ---------------------------------------------------------------------------
// k2b: chunk partial pooled sums, float4 rows.  Grid (NCH, BB), 128t.
// Each block sums 16 rows of 128 float4 (L2/DRAM mixed, coalesced).
// ---------------------------------------------------------------------------
__global__ void __launch_bounds__(128) k2b_combine() {
    int ci = blockIdx.x, b = blockIdx.y;
    int t4 = threadIdx.x;                  // float4 column (128 = 512 ch)
    const float4* base = (const float4*)(g_pooled + (long)b * NB * CC)
                         + (long)ci * 16 * 128 + t4;
    float4 acc = make_float4(0.f, 0.f, 0.f, 0.f);
    #pragma unroll
    for (int r = 0; r < 16; r++) {
        float4 d = base[r * 128];
        acc.x += d.x; acc.y += d.y; acc.z += d.z; acc.w += d.w;
    }
    ((float4*)g_pp)[(b * NCH + ci) * 128 + t4] = acc;
}

// ---------------------------------------------------------------------------
// k2c: Zinv from g_z (NB=512 = 2 loads/thread); pooled = sum chunks * Zinv;
// gate = Wv @ pooled + bv.  Grid (64, BB), 256t.
// ---------------------------------------------------------------------------
__global__ void __launch_bounds__(256) k2c_gate(const float* __restrict__ Wv,
                                                const float* __restrict__ bv) {
    __shared__ float pooled[CC];
    __shared__ float red[8];
    __shared__ float s_zinv;
    int b = blockIdx.y, tid = threadIdx.x;
    int lane = tid & 31, warp = tid >> 5;

    float z = g_z[b * NB + tid] + g_z[b * NB + tid + 256];
    #pragma unroll
    for (int off = 16; off; off >>= 1) z += __shfl_xor_sync(0xffffffffu, z, off);
    if (lane == 0) red[warp] = z;
    __syncthreads();
    if (tid == 0) {
        float s = 0.f;
        #pragma unroll
        for (int i = 0; i < 8; i++) s += red[i];
        s_zinv = 1.f / s;
    }
    __syncthreads();
    float zinv = s_zinv;
    #pragma unroll
    for (int h = 0; h < 2; h++) {
        int c = tid + h * 256;
        float a = 0.f;
        #pragma unroll
        for (int ci = 0; ci < NCH; ci++) a += g_pp[(b * NCH + ci) * CC + c];
        pooled[c] = a * zinv;
    }
    __syncthreads();
    int o = blockIdx.x * 8 + warp;
    float a = 0.f;
    #pragma unroll
    for (int jj = lane; jj < CC; jj += 32) a = fmaf(Wv[o * CC + jj], pooled[jj], a);
    #pragma unroll
    for (int off = 16; off; off >>= 1) a += __shfl_xor_sync(0xffffffffu, a, off);
    if (lane == 0) g_gate[b * CC + o] = a + bv[o];
}

// ---------------------------------------------------------------------------
// k3: out = x * gate[b,c]  (R6-proven: 2x float4 per thread, streaming hints)
// ---------------------------------------------------------------------------
__global__ void __launch_bounds__(256) k3_scale(const float4* __restrict__ x,
                                                float4* __restrict__ out) {
    int i0 = blockIdx.x * 512 + threadIdx.x;
    int i1 = i0 + 256;
    float4 a = __ldcs(x + i0);
    float4 d = __ldcs(x + i1);
    float ga = g_gate[i0 >> 12];           // 4096 float4 per (b,c)
    float gd = g_gate[i1 >> 12];
    a.x *= ga; a.y *= ga; a.z *= ga; a.w *= ga;
    d.x *= gd; d.y *= gd; d.z *= gd; d.w *= gd;
    __stcs(out + i0, a);
    __stcs(out + i1, d);
}

// ---------------------------------------------------------------------------
extern "C" void kernel_launch(void* const* d_in, const int* in_sizes, int n_in,
                              void* d_out, int out_size) {
    const float* x   = (const float*)d_in[0];
    const float* ctx = (const float*)d_in[1];
    const float* Wq  = (const float*)d_in[2];
    const float* bq  = (const float*)d_in[3];
    const float* Wk  = (const float*)d_in[4];
    // d_in[5] = bk: constant logit shift per batch -> cancels in softmax
    const float* Wv  = (const float*)d_in[6];
    const float* bv  = (const float*)d_in[7];

    k0a_q<<<dim3(64, BB), 256>>>(ctx, Wq, bq);
    k0b_qk<<<dim3(8, BB), 256>>>(Wk);
    k1_fused<<<dim3(NB, BB), 256>>>(x);
    k2b_combine<<<dim3(NCH, BB), 128>>>();
    k2c_gate<<<dim3(64, BB), 256>>>(Wv, bv);
    k3_scale<<<(BB * CC * HWN) / (4 * 512), 256>>>((const float4*)x, (float4*)d_out);
}

// round 11
// speedup vs baseline: 1.2524x; 1.0789x over previous
#include <cuda_runtime.h>
#include <cuda_bf16.h>

#define CC 512      // channels
#define DD 512      // context dim
#define BB 8        // batch
#define HWN 16384   // H*W
#define T_SUB 4     // 16-pos sub-tiles per k1 block (R6-proven)
#define NB 256      // k1 blocks per batch = HWN / (16*T_SUB)
#define NCH 32      // k2b chunks per batch (8 rows each)
#define STRIDE 17   // smem row stride (conflict-free)
#define SCALE_C 0.04419417382415922f  // 512^-0.5

// Scratch (device globals; no allocations allowed)
__device__ float g_q[BB * CC];               // SCALE * (ctx @ Wq^T + bq)
__device__ float g_qk[BB * CC];              // SCALE * (q @ Wk)
__device__ float g_pooled[BB * NB * CC];     // per-block unnormalized pooled sums (4.2MB)
__device__ float g_z[BB * NB];               // per-block sum exp(logit)
__device__ float g_pp[BB * NCH * CC];        // chunk partial pooled
__device__ float g_gate[BB * CC];            // final channel gates

// ---------------------------------------------------------------------------
// k0a: q_scaled[b][o] = SCALE * (ctx[b]·Wq[o,:] + bq[o]).  Grid (64, BB), 256t.
// ---------------------------------------------------------------------------
__global__ void __launch_bounds__(256) k0a_q(const float* __restrict__ ctx,
                                             const float* __restrict__ Wq,
                                             const float* __restrict__ bq) {
    __shared__ float ctxs[DD];
    int b = blockIdx.y, tid = threadIdx.x;
    int lane = tid & 31, warp = tid >> 5;      // 8 warps
    ctxs[tid] = ctx[b * DD + tid];
    ctxs[tid + 256] = ctx[b * DD + tid + 256];
    __syncthreads();
    int o = blockIdx.x * 8 + warp;
    float a = 0.f;
    #pragma unroll
    for (int j = lane; j < DD; j += 32) a += Wq[o * DD + j] * ctxs[j];
    #pragma unroll
    for (int off = 16; off; off >>= 1) a += __shfl_xor_sync(0xffffffffu, a, off);
    if (lane == 0) g_q[b * CC + o] = (a + bq[o]) * SCALE_C;
}

// ---------------------------------------------------------------------------
// k0b: qk[b][c] = sum_o q_s[b][o] * Wk[o][c].  Grid (8 cchunks, BB), 256t.
// ---------------------------------------------------------------------------
__global__ void __launch_bounds__(256) k0b_qk(const float* __restrict__ Wk) {
    __shared__ float qs[CC];
    __shared__ float red[4][64];
    int b = blockIdx.y, tid = threadIdx.x;
    qs[tid] = g_q[b * CC + tid];
    qs[tid + 256] = g_q[b * CC + tid + 256];
    __syncthreads();
    int cl = tid & 63, og = tid >> 6;          // 4 o-groups of 128
    int c = blockIdx.x * 64 + cl;
    float a = 0.f;
    int o0 = og * 128;
    #pragma unroll 8
    for (int o = 0; o < 128; o++) a = fmaf(qs[o0 + o], Wk[(o0 + o) * CC + c], a);
    red[og][cl] = a;
    __syncthreads();
    if (og == 0) g_qk[b * CC + c] = red[0][cl] + red[1][cl] + red[2][cl] + red[3][cl];
}

// ---------------------------------------------------------------------------
// k1: fused logits + exp-weights (no max; |logit| small) + pooling, looped
// over T_SUB=4 sub-tiles of 16 positions. Grid (NB, BB), 256 threads.
// Identical to the proven R6 kernel EXCEPT x loads use default cache policy
// so the last-read ~L2-capacity stripe of x stays resident for k3 (which
// runs in reversed order and consumes it first).
// ---------------------------------------------------------------------------
__global__ void __launch_bounds__(256) k1_fused(const float* __restrict__ x) {
    __shared__ float xs[CC * STRIDE];      // 34816 B (reused per sub-tile)
    __shared__ float part[16][9];          // per-warp logit partials
    __shared__ float lw[16];               // exp(logit) for current sub-tile

    int blk = blockIdx.x, b = blockIdx.y;
    int tid = threadIdx.x;
    int v = tid & 3, g = tid >> 2, warp = tid >> 5, lane = tid & 31;

    const float* qkb = g_qk + b * CC;
    float qc[8];
    #pragma unroll
    for (int k = 0; k < 8; k++) qc[k] = __ldg(qkb + g + 64 * k);

    long base = (long)b * (CC * HWN) + blk * (16 * T_SUB) + v * 4;
    float pl0 = 0.f, pl1 = 0.f;            // pooled acc for c=tid, c=tid+256
    float zsum = 0.f;                      // valid in warp 0

    #pragma unroll
    for (int s = 0; s < T_SUB; s++) {
        // Phase 1: load 512ch x 16pos to smem, fuse logit partial dots
        float p0 = 0.f, p1 = 0.f, p2 = 0.f, p3 = 0.f;
        #pragma unroll
        for (int k = 0; k < 8; k++) {
            int c = g + 64 * k;
            float4 d = *(const float4*)(x + base + (long)c * HWN + s * 16);
            float* dst = xs + c * STRIDE + v * 4;
            dst[0] = d.x; dst[1] = d.y; dst[2] = d.z; dst[3] = d.w;
            p0 = fmaf(d.x, qc[k], p0); p1 = fmaf(d.y, qc[k], p1);
            p2 = fmaf(d.z, qc[k], p2); p3 = fmaf(d.w, qc[k], p3);
        }
        // reduce over the 8 channel-groups in this warp sharing v
        #pragma unroll
        for (int off = 4; off <= 16; off <<= 1) {
            p0 += __shfl_xor_sync(0xffffffffu, p0, off);
            p1 += __shfl_xor_sync(0xffffffffu, p1, off);
            p2 += __shfl_xor_sync(0xffffffffu, p2, off);
            p3 += __shfl_xor_sync(0xffffffffu, p3, off);
        }
        if (lane < 4) {                    // lane == v for lanes 0..3
            part[lane * 4 + 0][warp] = p0;
            part[lane * 4 + 1][warp] = p1;
            part[lane * 4 + 2][warp] = p2;
            part[lane * 4 + 3][warp] = p3;
        }
        __syncthreads();

        // Phase 2 (warp 0): finish logits, weights = exp(l), z partial
        if (warp == 0) {
            int t = lane & 15;
            float l = 0.f;
            #pragma unroll
            for (int i = 0; i < 8; i++) l += part[t][i];
            float w = __expf(l);
            if (lane < 16) lw[t] = w;
            float wz = (lane < 16) ? w : 0.f;
            #pragma unroll
            for (int off = 16; off; off >>= 1)
                wz += __shfl_xor_sync(0xffffffffu, wz, off);
            zsum += wz;
        }
        __syncthreads();

        // Phase 3: accumulate pooled partial from smem (2 channels/thread)
        {
            const float* r0 = xs + tid * STRIDE;
            const float* r1 = xs + (tid + 256) * STRIDE;
            #pragma unroll
            for (int t = 0; t < 16; t++) {
                float w = lw[t];
                pl0 = fmaf(w, r0[t], pl0);
                pl1 = fmaf(w, r1[t], pl1);
            }
        }
        __syncthreads();                   // xs reused next iteration
    }

    float* dst = g_pooled + ((long)(b * NB) + blk) * CC;
    dst[tid] = pl0;                        // cached: k2b reads these next
    dst[tid + 256] = pl1;
    if (tid == 0) g_z[b * NB + blk] = zsum;
}

// ---------------------------------------------------------------------------
// k2b: chunk partial pooled sums, float4 rows.  Grid (NCH, BB), 128t.
// Each block sums 8 rows of 128 float4 (L2-hot, coalesced).
// ---------------------------------------------------------------------------
__global__ void __launch_bounds__(128) k2b_combine() {
    int ci = blockIdx.x, b = blockIdx.y;
    int t4 = threadIdx.x;                  // float4 column (128 = 512 ch)
    const float4* base = (const float4*)(g_pooled + (long)b * NB * CC)
                         + (long)ci * 8 * 128 + t4;
    float4 acc = make_float4(0.f, 0.f, 0.f, 0.f);
    #pragma unroll
    for (int r = 0; r < 8; r++) {
        float4 d = base[r * 128];
        acc.x += d.x; acc.y += d.y; acc.z += d.z; acc.w += d.w;
    }
    ((float4*)g_pp)[(b * NCH + ci) * 128 + t4] = acc;
}

// ---------------------------------------------------------------------------
// k2c: Zinv from g_z (NB=256 = 1 load/thread); pooled = sum chunks * Zinv;
// gate = Wv @ pooled + bv.  Grid (64, BB), 256t.
// ---------------------------------------------------------------------------
__global__ void __launch_bounds__(256) k2c_gate(const float* __restrict__ Wv,
                                                const float* __restrict__ bv) {
    __shared__ float pooled[CC];
    __shared__ float red[8];
    __shared__ float s_zinv;
    int b = blockIdx.y, tid = threadIdx.x;
    int lane = tid & 31, warp = tid >> 5;

    float z = g_z[b * NB + tid];
    #pragma unroll
    for (int off = 16; off; off >>= 1) z += __shfl_xor_sync(0xffffffffu, z, off);
    if (lane == 0) red[warp] = z;
    __syncthreads();
    if (tid == 0) {
        float s = 0.f;
        #pragma unroll
        for (int i = 0; i < 8; i++) s += red[i];
        s_zinv = 1.f / s;
    }
    __syncthreads();
    float zinv = s_zinv;
    #pragma unroll
    for (int h = 0; h < 2; h++) {
        int c = tid + h * 256;
        float a = 0.f;
        #pragma unroll
        for (int ci = 0; ci < NCH; ci++) a += g_pp[(b * NCH + ci) * CC + c];
        pooled[c] = a * zinv;
    }
    __syncthreads();
    int o = blockIdx.x * 8 + warp;
    float a = 0.f;
    #pragma unroll
    for (int jj = lane; jj < CC; jj += 32) a = fmaf(Wv[o * CC + jj], pooled[jj], a);
    #pragma unroll
    for (int off = 16; off; off >>= 1) a += __shfl_xor_sync(0xffffffffu, a, off);
    if (lane == 0) g_gate[b * CC + o] = a + bv[o];
}

// ---------------------------------------------------------------------------
// k3: out = x * gate[b,c], GLOBALLY REVERSED order: the first k3 blocks read
// exactly the x region k1 touched last (still L2-resident).  Loads default
// policy (hit leftover L2); stores streaming.
// ---------------------------------------------------------------------------
__global__ void __launch_bounds__(256) k3_scale(const float4* __restrict__ x,
                                                float4* __restrict__ out) {
    int rb = 16383 - blockIdx.x;           // reversed block index (16384 blocks)
    int i0 = rb * 1024 + threadIdx.x;      // 4 float4 per thread, 1024 per block
    float ga = g_gate[i0 >> 12];           // 4096 float4 per (b,c)
    float gb = g_gate[(i0 + 256) >> 12];
    float gc = g_gate[(i0 + 512) >> 12];
    float gd = g_gate[(i0 + 768) >> 12];
    float4 a = x[i0];
    float4 bq4 = x[i0 + 256];
    float4 c = x[i0 + 512];
    float4 d = x[i0 + 768];
    a.x *= ga; a.y *= ga; a.z *= ga; a.w *= ga;
    bq4.x *= gb; bq4.y *= gb; bq4.z *= gb; bq4.w *= gb;
    c.x *= gc; c.y *= gc; c.z *= gc; c.w *= gc;
    d.x *= gd; d.y *= gd; d.z *= gd; d.w *= gd;
    __stcs(out + i0, a);
    __stcs(out + i0 + 256, bq4);
    __stcs(out + i0 + 512, c);
    __stcs(out + i0 + 768, d);
}

// ---------------------------------------------------------------------------
extern "C" void kernel_launch(void* const* d_in, const int* in_sizes, int n_in,
                              void* d_out, int out_size) {
    const float* x   = (const float*)d_in[0];
    const float* ctx = (const float*)d_in[1];
    const float* Wq  = (const float*)d_in[2];
    const float* bq  = (const float*)d_in[3];
    const float* Wk  = (const float*)d_in[4];
    // d_in[5] = bk: constant logit shift per batch -> cancels in softmax
    const float* Wv  = (const float*)d_in[6];
    const float* bv  = (const float*)d_in[7];

    k0a_q<<<dim3(64, BB), 256>>>(ctx, Wq, bq);
    k0b_qk<<<dim3(8, BB), 256>>>(Wk);
    k1_fused<<<dim3(NB, BB), 256>>>(x);
    k2b_combine<<<dim3(NCH, BB), 128>>>();
    k2c_gate<<<dim3(64, BB), 256>>>(Wv, bv);
    k3_scale<<<16384, 256>>>((const float4*)x, (float4*)d_out);
}